// round 14
// baseline (speedup 1.0000x reference)
#include <cuda_runtime.h>
#include <cuda_bf16.h>
#include <cstdint>

typedef __nv_bfloat16 bf16;

#define B_ 32
#define T_ 512
#define E_ 512
#define H_ 1024
#define O_ 128
#define NCTA 128
#define KTOT 1536          // 512 (e) + 1024 (h)
#define SW 1544            // As row stride (elems); conflict-free ldmatrix
#define SWE 520            // We row stride (elems)
#define GST 36             // gates row stride (floats); float4-aligned
#define GPL16 (16 * GST)   // gate half-plane floats (16 batch rows)

// ---------------- scratch (static device globals; no allocs) ----------------
__device__ __align__(16) bf16  g_e[B_ * T_ * E_];              // embeddings bf16 [B][T][E]
__device__ __align__(16) bf16  g_Wc[(size_t)NCTA * 32 * KTOT]; // per-CTA packed [Wih|Whh]
__device__ __align__(16) bf16  g_Wo[O_ * H_];                  // W_lin[:,H:2H]
__device__ __align__(16) bf16  g_Wv[O_ * H_];                  // W_lin[:,0:H]
__device__ __align__(16) bf16  g_hs[(size_t)B_ * T_ * H_];     // hidden states [B][T][H]
__device__ __align__(16) bf16  g_hbuf[2][B_ * H_];             // h double buffer
__device__ float g_vc[B_ * O_];
__device__ __align__(128) int g_arrive[2][NCTA * 32];          // per-half flags, 128B apart

// ---------------- PTX helpers ----------------
__device__ __forceinline__ uint32_t smem_u32(const void* p) {
    return (uint32_t)__cvta_generic_to_shared(p);
}
__device__ __forceinline__ void ldm_x4(uint32_t* r, uint32_t a) {
    asm volatile("ldmatrix.sync.aligned.m8n8.x4.shared.b16 {%0,%1,%2,%3}, [%4];"
                 : "=r"(r[0]), "=r"(r[1]), "=r"(r[2]), "=r"(r[3]) : "r"(a));
}
__device__ __forceinline__ void mma16816(float* d, const uint32_t* a, const uint32_t* b) {
    asm volatile(
        "mma.sync.aligned.m16n8k16.row.col.f32.bf16.bf16.f32 "
        "{%0,%1,%2,%3}, {%4,%5,%6,%7}, {%8,%9}, {%0,%1,%2,%3};\n"
        : "+f"(d[0]), "+f"(d[1]), "+f"(d[2]), "+f"(d[3])
        : "r"(a[0]), "r"(a[1]), "r"(a[2]), "r"(a[3]), "r"(b[0]), "r"(b[1]));
}
__device__ __forceinline__ float sigmoidf_(float x) { return 1.f / (1.f + __expf(-x)); }

// ------------- prep1 (launch #0): init state + embedding gather -------------
__global__ void k_prep1(const int* __restrict__ tok, const float* __restrict__ emb) {
    int i = blockIdx.x * 256 + threadIdx.x;   // B*T*E/4 quads
    if (i < 2 * NCTA * 32) ((int*)g_arrive)[i] = 0;
    if (i < 2 * B_ * H_ / 8) ((uint4*)g_hbuf)[i] = make_uint4(0, 0, 0, 0);
    int m = i >> 7;                           // row in [0, B*T)
    int q = i & 127;
    int t = tok[m];
    float4 v = *(const float4*)(emb + (size_t)t * E_ + q * 4);
    __nv_bfloat162* d2 = (__nv_bfloat162*)(g_e + (size_t)m * E_ + q * 4);
    d2[0] = __floats2bfloat162_rn(v.x, v.y);
    d2[1] = __floats2bfloat162_rn(v.z, v.w);
}

// ------- prep2 (launch #1): pack [W_ih | W_hh] gate rows per CTA -> g_Wc -------
// packed row r of CTA c: jl = r>>2, gate g = r&3  ->  original row g*H + c*8 + jl
__global__ void k_prep2(const float* __restrict__ wih, const float* __restrict__ whh) {
    int idx = blockIdx.x * 256 + threadIdx.x;          // NCTA*32*KTOT/8 items
    int j = idx * 8;
    int k = j % KTOT;
    int r = (j / KTOT) & 31;
    int c = j / (KTOT * 32);
    int row = (r & 3) * H_ + c * 8 + (r >> 2);
    const float* src = (k < E_) ? (wih + (size_t)row * E_ + k)
                                : (whh + (size_t)row * H_ + (k - E_));
    float4 a = *(const float4*)src;
    float4 b = *(const float4*)(src + 4);
    __nv_bfloat162 o[4];
    o[0] = __floats2bfloat162_rn(a.x, a.y);
    o[1] = __floats2bfloat162_rn(a.z, a.w);
    o[2] = __floats2bfloat162_rn(b.x, b.y);
    o[3] = __floats2bfloat162_rn(b.z, b.w);
    *(uint4*)(g_Wc + (size_t)j) = *(uint4*)o;
}

// ------------- prep3 (launch #2): split W_lin into Wv / Wo -------------
__global__ void k_prep3(const float* __restrict__ wlin) {
    int idx = blockIdx.x * 256 + threadIdx.x;   // O*2H/4 items
    int j = idx * 4;
    int o = j >> 11;
    int k = j & 2047;
    float4 v = *(const float4*)(wlin + j);
    __nv_bfloat162 p0 = __floats2bfloat162_rn(v.x, v.y);
    __nv_bfloat162 p1 = __floats2bfloat162_rn(v.z, v.w);
    bf16* dst = (k < H_) ? (g_Wv + o * H_ + k) : (g_Wo + o * H_ + (k - H_));
    ((__nv_bfloat162*)dst)[0] = p0;
    ((__nv_bfloat162*)dst)[1] = p1;
}

// ---------------- fused persistent LSTM (launch #3, profiled) ----------------
// 128 CTAs x 256 threads = 8 warps. DUAL-WAVE: batch rows 0-15 (half0) and
// 16-31 (half1) are independent LSTMs, phase-shifted within each step so each
// half's barrier/flag/h-load latency hides under the other half's compute.
// Warp w: full N=32 gate rows, strided 1/8 of K; h-weight frags in registers
// (bh[8][8], shared by both halves). Gate buffer (16-row planes) reused A/B.
#define SMEM_LSTM (32 * SW * 2 + 32 * SWE * 2 + 8 * GPL16 * 4)

__global__ void __launch_bounds__(256, 1) k_lstm(const float* __restrict__ bih,
                                                 const float* __restrict__ bhh) {
    extern __shared__ char sm[];
    bf16*  As    = (bf16*)sm;                               // 32 x SW
    bf16*  We    = (bf16*)(sm + 32 * SW * 2);               // 32 x SWE (e-weights)
    float* gates = (float*)(sm + 32 * SW * 2 + 32 * SWE * 2);
    const int tid = threadIdx.x, lane = tid & 31, w = tid >> 5;
    const int cta = blockIdx.x;
    const int jl = tid & 7;
    const int gcol = cta * 8 + jl;
    const int brow = (tid & 127) >> 3;                      // my gate-plane row (0..15)
    const int bglob = (tid < 128) ? brow : (16 + brow);     // my global batch row

    // ---- init: full weight slice 32x1536 -> As (temporarily) ----
    for (int i = tid; i < 6144; i += 256) {
        int r = i / 192, q = i - r * 192;
        *(uint4*)&As[r * SW + q * 8] = *(const uint4*)(g_Wc + ((size_t)cta * 32 + r) * KTOT + q * 8);
    }
    __syncthreads();

    // hoist h-part B fragments to registers (chunks w+32..w+88)
    const int bro0 = ((lane & 7) + ((lane >> 4) << 3));
    const int bco  = ((lane >> 3) & 1) * 8;
    uint32_t bh[8][8];
#pragma unroll
    for (int j = 0; j < 8; j++) {
        int col = 512 + 16 * w + 128 * j;
#pragma unroll
        for (int nt = 0; nt < 2; nt++)
            ldm_x4(&bh[j][nt * 4], smem_u32(&As[(nt * 16 + bro0) * SW + col + bco]));
    }
    // e-part weights gmem -> We (32 x 512)
    for (int i = tid; i < 2048; i += 256) {
        int r = i >> 6, q = i & 63;
        *(uint4*)&We[r * SWE + q * 8] = *(const uint4*)(g_Wc + ((size_t)cta * 32 + r) * KTOT + q * 8);
    }
    const float bs0 = bih[gcol]          + bhh[gcol];
    const float bs1 = bih[H_ + gcol]     + bhh[H_ + gcol];
    const float bs2 = bih[2 * H_ + gcol] + bhh[2 * H_ + gcol];
    const float bs3 = bih[3 * H_ + gcol] + bhh[3 * H_ + gcol];
    __syncthreads();   // bh reads done + We written before As reuse

    const int arow0 = (lane & 15) * SW + ((lane >> 4) * 8);

    float acc0[4][4], acc1[4][4];

    // ---- prologue: stage e(0) all rows + zero h0-region rows 0..15 ----
#pragma unroll
    for (int j = 0; j < 8; j++) {
        int idx = j * 256 + tid; int er = idx >> 6, eq = idx & 63;
        uint4 ev = *(const uint4*)(g_e + ((size_t)er * T_) * E_ + eq * 8);
        *(uint4*)&As[er * SW + eq * 8] = ev;
    }
#pragma unroll
    for (int j = 0; j < 8; j++) {
        int idx = j * 256 + tid; int r = idx >> 7, hq = idx & 127;
        *(uint4*)&As[r * SW + 512 + hq * 8] = make_uint4(0, 0, 0, 0);
    }
    __syncthreads();

    // e-mma for t=0, both halves
#pragma unroll
    for (int h = 0; h < 2; h++) {
        float (*ac)[4] = h ? acc1 : acc0;
        int hbase = h * 16 * SW;
#pragma unroll
        for (int n = 0; n < 4; n++)
#pragma unroll
            for (int r = 0; r < 4; r++) ac[n][r] = 0.f;
#pragma unroll
        for (int j = 0; j < 4; j++) {
            int col = (w + 8 * j) * 16;
            uint32_t be[8], af[4];
            ldm_x4(be,     smem_u32(&We[bro0 * SWE + col + bco]));
            ldm_x4(be + 4, smem_u32(&We[(16 + bro0) * SWE + col + bco]));
            ldm_x4(af, smem_u32(&As[hbase + arow0 + col]));
            mma16816(ac[0], af, be);
            mma16816(ac[1], af, be + 2);
            mma16816(ac[2], af, be + 4);
            mma16816(ac[3], af, be + 6);
        }
    }

    float creg = 0.f;     // tid<128: half0 cell state; tid>=128: half1
    for (int t = 0; t < T_; t++) {
        const bf16* hsrc = g_hbuf[t & 1];
        bf16*       hdst = g_hbuf[(t + 1) & 1];
        const int tn = (t + 1 < T_) ? t + 1 : T_ - 1;

        // ================= A phase (half 0) =================
        // issue LDG h1(t) rows 16..31 and e(t+1) (latency hidden by h-mma half0)
        uint4 hreg[8], ereg[8];
#pragma unroll
        for (int j = 0; j < 8; j++) {
            int idx = j * 256 + tid; int r = idx >> 7, hq = idx & 127;
            hreg[j] = __ldcg((const uint4*)(hsrc + (size_t)(16 + r) * H_ + hq * 8));
        }
#pragma unroll
        for (int j = 0; j < 8; j++) {
            int idx = j * 256 + tid; int er = idx >> 6, eq = idx & 63;
            ereg[j] = __ldcg((const uint4*)(g_e + ((size_t)er * T_ + tn) * E_ + eq * 8));
        }
        // h-mma half0: acc0 (holds e-part for t) += h0(t) @ Whh
#pragma unroll
        for (int j = 0; j < 8; j++) {
            int col = 512 + 16 * w + 128 * j;
            uint32_t af[4];
            ldm_x4(af, smem_u32(&As[arow0 + col]));
            mma16816(acc0[0], af, bh[j]);
            mma16816(acc0[1], af, bh[j] + 2);
            mma16816(acc0[2], af, bh[j] + 4);
            mma16816(acc0[3], af, bh[j] + 6);
        }
        // stage h1(t) and e(t+1)
#pragma unroll
        for (int j = 0; j < 8; j++) {
            int idx = j * 256 + tid; int r = idx >> 7, hq = idx & 127;
            *(uint4*)&As[(16 + r) * SW + 512 + hq * 8] = hreg[j];
        }
#pragma unroll
        for (int j = 0; j < 8; j++) {
            int idx = j * 256 + tid; int er = idx >> 6, eq = idx & 63;
            *(uint4*)&As[er * SW + eq * 8] = ereg[j];
        }
        // gates0 (16-row plane)
        {
            float* gp = gates + w * GPL16;
            int mr = lane >> 2, mc = (lane & 3) * 2;
#pragma unroll
            for (int n = 0; n < 4; n++) {
                *(float2*)&gp[mr * GST + n * 8 + mc]       = make_float2(acc0[n][0], acc0[n][1]);
                *(float2*)&gp[(mr + 8) * GST + n * 8 + mc] = make_float2(acc0[n][2], acc0[n][3]);
            }
        }
        __syncthreads();                       // S1: gates0 + h1/e staged visible

        bf16 hb0;
        if (tid < 128) {                       // cell half0
            float pi = bs0, pf = bs1, pg = bs2, po = bs3;
#pragma unroll
            for (int p = 0; p < 8; p++) {
                float4 v = *(const float4*)(gates + p * GPL16 + brow * GST + jl * 4);
                pi += v.x; pf += v.y; pg += v.z; po += v.w;
            }
            float ig = sigmoidf_(pi), fg = sigmoidf_(pf), og = sigmoidf_(po);
            float gg = tanhf(pg);
            creg = fg * creg + ig * gg;
            hb0 = __float2bfloat16(og * tanhf(creg));
            hdst[bglob * H_ + gcol] = hb0;
        }
        __syncthreads();                       // S2: h0(t+1) stores done block-wide
        if (tid == 0) {
            asm volatile("st.release.gpu.global.b32 [%0], %1;"
                         :: "l"(&g_arrive[0][cta * 32]), "r"(t + 1) : "memory");
        }
        if (tid < 128) __stcs(&g_hs[((size_t)bglob * T_ + t) * H_ + gcol], hb0);

        // e-mma half0 for t+1 (shadow for release0 propagation)
#pragma unroll
        for (int n = 0; n < 4; n++)
#pragma unroll
            for (int r = 0; r < 4; r++) acc0[n][r] = 0.f;
#pragma unroll
        for (int j = 0; j < 4; j++) {
            int col = (w + 8 * j) * 16;
            uint32_t be[8], af[4];
            ldm_x4(be,     smem_u32(&We[bro0 * SWE + col + bco]));
            ldm_x4(be + 4, smem_u32(&We[(16 + bro0) * SWE + col + bco]));
            ldm_x4(af, smem_u32(&As[arow0 + col]));
            mma16816(acc0[0], af, be);
            mma16816(acc0[1], af, be + 2);
            mma16816(acc0[2], af, be + 4);
            mma16816(acc0[3], af, be + 6);
        }

        // ================= B phase (half 1) =================
        // h-mma half1: acc1 += h1(t) @ Whh (rows 16..31, staged in A)
#pragma unroll
        for (int j = 0; j < 8; j++) {
            int col = 512 + 16 * w + 128 * j;
            uint32_t af[4];
            ldm_x4(af, smem_u32(&As[16 * SW + arow0 + col]));
            mma16816(acc1[0], af, bh[j]);
            mma16816(acc1[1], af, bh[j] + 2);
            mma16816(acc1[2], af, bh[j] + 4);
            mma16816(acc1[3], af, bh[j] + 6);
        }
        // gates1 (same planes, cell0 readers done at S2)
        {
            float* gp = gates + w * GPL16;
            int mr = lane >> 2, mc = (lane & 3) * 2;
#pragma unroll
            for (int n = 0; n < 4; n++) {
                *(float2*)&gp[mr * GST + n * 8 + mc]       = make_float2(acc1[n][0], acc1[n][1]);
                *(float2*)&gp[(mr + 8) * GST + n * 8 + mc] = make_float2(acc1[n][2], acc1[n][3]);
            }
        }
        __syncthreads();                       // S3: gates1 visible

        bf16 hb1;
        if (tid >= 128) {                      // cell half1
            float pi = bs0, pf = bs1, pg = bs2, po = bs3;
#pragma unroll
            for (int p = 0; p < 8; p++) {
                float4 v = *(const float4*)(gates + p * GPL16 + brow * GST + jl * 4);
                pi += v.x; pf += v.y; pg += v.z; po += v.w;
            }
            float ig = sigmoidf_(pi), fg = sigmoidf_(pf), og = sigmoidf_(po);
            float gg = tanhf(pg);
            creg = fg * creg + ig * gg;
            hb1 = __float2bfloat16(og * tanhf(creg));
            hdst[bglob * H_ + gcol] = hb1;
        }
        __syncthreads();                       // S4: h1(t+1) stores done block-wide
        if (tid == 0) {
            asm volatile("st.release.gpu.global.b32 [%0], %1;"
                         :: "l"(&g_arrive[1][cta * 32]), "r"(t + 1) : "memory");
        }
        if (tid >= 128) __stcs(&g_hs[((size_t)bglob * T_ + t) * H_ + gcol], hb1);

        // poll flags0 >= t+1 (released a half-phase ago -> near-instant)
        if (tid < NCTA) {
            const int* fp = &g_arrive[0][tid * 32];
            int v;
            do {
                asm volatile("ld.acquire.gpu.global.b32 %0, [%1];" : "=r"(v) : "l"(fp));
            } while (v < t + 1);
        }
        __syncthreads();                       // S5: flags0 confirmed block-wide

        // LDG h0(t+1) rows 0..15 (latency hidden by e-mma half1)
#pragma unroll
        for (int j = 0; j < 8; j++) {
            int idx = j * 256 + tid; int r = idx >> 7, hq = idx & 127;
            hreg[j] = __ldcg((const uint4*)(hdst + (size_t)r * H_ + hq * 8));
        }
        // e-mma half1 for t+1
#pragma unroll
        for (int n = 0; n < 4; n++)
#pragma unroll
            for (int r = 0; r < 4; r++) acc1[n][r] = 0.f;
#pragma unroll
        for (int j = 0; j < 4; j++) {
            int col = (w + 8 * j) * 16;
            uint32_t be[8], af[4];
            ldm_x4(be,     smem_u32(&We[bro0 * SWE + col + bco]));
            ldm_x4(be + 4, smem_u32(&We[(16 + bro0) * SWE + col + bco]));
            ldm_x4(af, smem_u32(&As[16 * SW + arow0 + col]));
            mma16816(acc1[0], af, be);
            mma16816(acc1[1], af, be + 2);
            mma16816(acc1[2], af, be + 4);
            mma16816(acc1[3], af, be + 6);
        }
        // stage h0(t+1)
#pragma unroll
        for (int j = 0; j < 8; j++) {
            int idx = j * 256 + tid; int r = idx >> 7, hq = idx & 127;
            *(uint4*)&As[r * SW + 512 + hq * 8] = hreg[j];
        }
        // poll flags1 >= t+1 (released above; mostly propagated by now)
        if (tid < NCTA) {
            const int* fp = &g_arrive[1][tid * 32];
            int v;
            do {
                asm volatile("ld.acquire.gpu.global.b32 %0, [%1];" : "=r"(v) : "l"(fp));
            } while (v < t + 1);
        }
        __syncthreads();                       // S6: h0 staged + flags1 confirmed
    }
}

// -------- bf16 NT mma GEMM (sync loads): C = A*B^T (launch #4) --------
__global__ void __launch_bounds__(128) k_gemm(
    const bf16* __restrict__ A, const bf16* __restrict__ Bm, float* __restrict__ C,
    int M, int N, int K)
{
    __shared__ __align__(16) bf16 As2[64 * 40];
    __shared__ __align__(16) bf16 Bs2[64 * 40];
    const int tid = threadIdx.x, lane = tid & 31, w = tid >> 5;
    const int bm = blockIdx.x * 64, bn = blockIdx.y * 64;
    const int wm = (w & 1) * 32, wn = (w >> 1) * 32;

    float acc[2][4][4];
#pragma unroll
    for (int i = 0; i < 2; i++)
#pragma unroll
        for (int j = 0; j < 4; j++)
#pragma unroll
            for (int r = 0; r < 4; r++) acc[i][j][r] = 0.f;

    for (int k0 = 0; k0 < K; k0 += 32) {
#pragma unroll
        for (int c = tid; c < 256; c += 128) {
            int r = c >> 2, q = c & 3;
            *(uint4*)&As2[r * 40 + q * 8] = *(const uint4*)(A + (size_t)(bm + r) * K + k0 + q * 8);
            *(uint4*)&Bs2[r * 40 + q * 8] = *(const uint4*)(Bm + (size_t)(bn + r) * K + k0 + q * 8);
        }
        __syncthreads();
#pragma unroll
        for (int kk = 0; kk < 32; kk += 16) {
            uint32_t af[2][4], bfr[4][2];
#pragma unroll
            for (int i = 0; i < 2; i++)
                ldm_x4(af[i], smem_u32(&As2[(wm + i * 16 + (lane & 15)) * 40 + kk + (lane >> 4) * 8]));
#pragma unroll
            for (int j = 0; j < 2; j++) {
                int row = wn + j * 16 + (lane & 7) + ((lane >> 4) << 3);
                int col = kk + ((lane >> 3) & 1) * 8;
                uint32_t r4[4];
                ldm_x4(r4, smem_u32(&Bs2[row * 40 + col]));
                bfr[j * 2][0] = r4[0]; bfr[j * 2][1] = r4[1];
                bfr[j * 2 + 1][0] = r4[2]; bfr[j * 2 + 1][1] = r4[3];
            }
#pragma unroll
            for (int i = 0; i < 2; i++)
#pragma unroll
                for (int j = 0; j < 4; j++) mma16816(acc[i][j], af[i], bfr[j]);
        }
        __syncthreads();
    }
#pragma unroll
    for (int i = 0; i < 2; i++)
#pragma unroll
        for (int j = 0; j < 4; j++) {
            int cN = bn + wn + j * 8 + (lane & 3) * 2;
#pragma unroll
            for (int p = 0; p < 2; p++) {
                int rr = bm + wm + i * 16 + (lane >> 2) + p * 8;
                C[(size_t)rr * N + cN]     = acc[i][j][2 * p + 0];
                C[(size_t)rr * N + cN + 1] = acc[i][j][2 * p + 1];
            }
        }
}

// -------- verb logits (launch #5) --------
__global__ void k_vc(const int* __restrict__ vidx, const float* __restrict__ blin) {
    __shared__ bf16 vrow[H_];
    int b = blockIdx.x, tid = threadIdx.x;
    int t = vidx[b];
    for (int i = tid; i < H_; i += 128) vrow[i] = g_hs[((size_t)b * T_ + t) * H_ + i];
    __syncthreads();
    float s = 0.f;
    const uint4* wr4 = (const uint4*)(g_Wv + (size_t)tid * H_);
    const uint4* hv4 = (const uint4*)vrow;
#pragma unroll 4
    for (int k = 0; k < H_ / 8; k++) {
        uint4 wv = wr4[k];
        uint4 hv = hv4[k];
        const __nv_bfloat162* wp = (const __nv_bfloat162*)&wv;
        const __nv_bfloat162* hp = (const __nv_bfloat162*)&hv;
#pragma unroll
        for (int q = 0; q < 4; q++) {
            s += __bfloat162float(wp[q].x) * __bfloat162float(hp[q].x)
               + __bfloat162float(wp[q].y) * __bfloat162float(hp[q].y);
        }
    }
    g_vc[b * O_ + tid] = s + blin[tid];
}

// -------- fused add-verb-logits + log_softmax (launch #6) --------
__global__ void k_lsm(float* __restrict__ out) {
    int m = blockIdx.x, tid = threadIdx.x, w = tid >> 5;
    int b = m >> 9;
    float x = out[(size_t)m * O_ + tid] + g_vc[b * O_ + tid];
    float mx = x;
#pragma unroll
    for (int o = 16; o; o >>= 1) mx = fmaxf(mx, __shfl_xor_sync(0xffffffffu, mx, o));
    __shared__ float s1[4], s2[4];
    if ((tid & 31) == 0) s1[w] = mx;
    __syncthreads();
    mx = fmaxf(fmaxf(s1[0], s1[1]), fmaxf(s1[2], s1[3]));
    float e = __expf(x - mx);
    float sm = e;
#pragma unroll
    for (int o = 16; o; o >>= 1) sm += __shfl_xor_sync(0xffffffffu, sm, o);
    if ((tid & 31) == 0) s2[w] = sm;
    __syncthreads();
    sm = s2[0] + s2[1] + s2[2] + s2[3];
    out[(size_t)m * O_ + tid] = x - mx - __logf(sm);
}

extern "C" void kernel_launch(void* const* d_in, const int* in_sizes, int n_in,
                              void* d_out, int out_size) {
    const int*   tokens = (const int*)d_in[0];
    const int*   vidx   = (const int*)d_in[1];
    const float* emb    = (const float*)d_in[2];
    const float* W_ih   = (const float*)d_in[3];
    const float* W_hh   = (const float*)d_in[4];
    const float* b_ih   = (const float*)d_in[5];
    const float* b_hh   = (const float*)d_in[6];
    const float* W_lin  = (const float*)d_in[7];
    const float* b_lin  = (const float*)d_in[8];
    float* out = (float*)d_out;

    static int smem_set = 0;
    if (!smem_set) {
        cudaFuncSetAttribute(k_lstm, cudaFuncAttributeMaxDynamicSharedMemorySize, SMEM_LSTM);
        smem_set = 1;
    }

    // #0: init + gather
    k_prep1<<<(B_ * T_ * E_ / 4) / 256, 256>>>(tokens, emb);
    // #1: pack [W_ih|W_hh] per CTA (float4-friendly gate order)
    k_prep2<<<(NCTA * 32 * KTOT / 8) / 256, 256>>>(W_ih, W_hh);
    // #2: split W_lin
    k_prep3<<<(O_ * 2 * H_ / 4) / 256, 256>>>(W_lin);
    // #3: fused persistent dual-wave LSTM (profiled slot)
    k_lstm<<<NCTA, 256, SMEM_LSTM>>>(b_ih, b_hh);
    // #4: out-part logits straight into d_out
    {
        dim3 grid(16384 / 64, 128 / 64);
        k_gemm<<<grid, 128>>>(g_hs, g_Wo, out, 16384, 128, 1024);
    }
    // #5/#6: verb logits + fused log_softmax
    k_vc<<<B_, 128>>>(vidx, b_lin);
    k_lsm<<<B_ * T_, 128>>>(out);
}

// round 15
// speedup vs baseline: 1.3766x; 1.3766x over previous
#include <cuda_runtime.h>
#include <cuda_bf16.h>
#include <cstdint>

typedef __nv_bfloat16 bf16;

#define B_ 32
#define T_ 512
#define E_ 512
#define H_ 1024
#define O_ 128
#define NCTA 128
#define KTOT 1536          // 512 (e) + 1024 (h)
#define SW 1544            // As row stride (elems); conflict-free ldmatrix
#define SWE 520            // We row stride (elems)
#define SWO 1032           // Wo_s row stride (elems); 2064B % 128 = 16 -> conflict-free
#define GST 40             // gates row stride (floats)
#define GPL (32 * GST)     // gate plane floats
#define OST 12             // out-plane row stride (floats)
#define OPL (32 * OST)     // out plane floats

// ---------------- scratch (static device globals; no allocs) ----------------
__device__ __align__(16) bf16  g_e[B_ * T_ * E_];              // embeddings bf16 [B][T][E]
__device__ __align__(16) bf16  g_Wc[(size_t)NCTA * 32 * KTOT]; // per-CTA packed [Wih|Whh]
__device__ __align__(16) bf16  g_Wo[O_ * H_];                  // W_lin[:,H:2H]
__device__ __align__(16) bf16  g_Wv[O_ * H_];                  // W_lin[:,0:H]
__device__ __align__(16) bf16  g_hs[(size_t)B_ * T_ * H_];     // hidden states [B][T][H]
__device__ __align__(16) bf16  g_hbuf[2][B_ * H_];             // h double buffer
__device__ float g_vc[B_ * O_];
__device__ __align__(128) int g_arrive[NCTA * 32];             // 1 flag per CTA, 128B apart

// ---------------- PTX helpers ----------------
__device__ __forceinline__ uint32_t smem_u32(const void* p) {
    return (uint32_t)__cvta_generic_to_shared(p);
}
__device__ __forceinline__ void ldm_x4(uint32_t* r, uint32_t a) {
    asm volatile("ldmatrix.sync.aligned.m8n8.x4.shared.b16 {%0,%1,%2,%3}, [%4];"
                 : "=r"(r[0]), "=r"(r[1]), "=r"(r[2]), "=r"(r[3]) : "r"(a));
}
__device__ __forceinline__ void ldm_x2(uint32_t* r, uint32_t a) {
    asm volatile("ldmatrix.sync.aligned.m8n8.x2.shared.b16 {%0,%1}, [%2];"
                 : "=r"(r[0]), "=r"(r[1]) : "r"(a));
}
__device__ __forceinline__ void mma16816(float* d, const uint32_t* a, const uint32_t* b) {
    asm volatile(
        "mma.sync.aligned.m16n8k16.row.col.f32.bf16.bf16.f32 "
        "{%0,%1,%2,%3}, {%4,%5,%6,%7}, {%8,%9}, {%0,%1,%2,%3};\n"
        : "+f"(d[0]), "+f"(d[1]), "+f"(d[2]), "+f"(d[3])
        : "r"(a[0]), "r"(a[1]), "r"(a[2]), "r"(a[3]), "r"(b[0]), "r"(b[1]));
}
__device__ __forceinline__ float sigmoidf_(float x) { return 1.f / (1.f + __expf(-x)); }

// ------------- prep1 (launch #0): init state + embedding gather -------------
__global__ void k_prep1(const int* __restrict__ tok, const float* __restrict__ emb) {
    int i = blockIdx.x * 256 + threadIdx.x;   // B*T*E/4 quads
    if (i < NCTA * 32) g_arrive[i] = 0;
    if (i < 2 * B_ * H_ / 8) ((uint4*)g_hbuf)[i] = make_uint4(0, 0, 0, 0);
    int m = i >> 7;                           // row in [0, B*T)
    int q = i & 127;
    int t = tok[m];
    float4 v = *(const float4*)(emb + (size_t)t * E_ + q * 4);
    __nv_bfloat162* d2 = (__nv_bfloat162*)(g_e + (size_t)m * E_ + q * 4);
    d2[0] = __floats2bfloat162_rn(v.x, v.y);
    d2[1] = __floats2bfloat162_rn(v.z, v.w);
}

// ------- prep2 (launch #1): pack [W_ih | W_hh] gate rows per CTA -> g_Wc -------
// packed row r of CTA c: gate g = r>>3, jl = r&7  ->  original row g*H + c*8 + jl
__global__ void k_prep2(const float* __restrict__ wih, const float* __restrict__ whh) {
    int idx = blockIdx.x * 256 + threadIdx.x;          // NCTA*32*KTOT/8 items
    int j = idx * 8;
    int k = j % KTOT;
    int r = (j / KTOT) & 31;
    int c = j / (KTOT * 32);
    int row = (r >> 3) * H_ + c * 8 + (r & 7);
    const float* src = (k < E_) ? (wih + (size_t)row * E_ + k)
                                : (whh + (size_t)row * H_ + (k - E_));
    float4 a = *(const float4*)src;
    float4 b = *(const float4*)(src + 4);
    __nv_bfloat162 o[4];
    o[0] = __floats2bfloat162_rn(a.x, a.y);
    o[1] = __floats2bfloat162_rn(a.z, a.w);
    o[2] = __floats2bfloat162_rn(b.x, b.y);
    o[3] = __floats2bfloat162_rn(b.z, b.w);
    *(uint4*)(g_Wc + (size_t)j) = *(uint4*)o;
}

// ------------- prep3 (launch #2): split W_lin into Wv / Wo -------------
__global__ void k_prep3(const float* __restrict__ wlin) {
    int idx = blockIdx.x * 256 + threadIdx.x;   // O*2H/4 items
    int j = idx * 4;
    int o = j >> 11;
    int k = j & 2047;
    float4 v = *(const float4*)(wlin + j);
    __nv_bfloat162 p0 = __floats2bfloat162_rn(v.x, v.y);
    __nv_bfloat162 p1 = __floats2bfloat162_rn(v.z, v.w);
    bf16* dst = (k < H_) ? (g_Wv + o * H_ + k) : (g_Wo + o * H_ + (k - H_));
    ((__nv_bfloat162*)dst)[0] = p0;
    ((__nv_bfloat162*)dst)[1] = p1;
}

// ---------------- fused persistent LSTM + output proj (launch #3) ----------------
// 128 CTAs x 256 threads = 8 warps (R7 layout). Warp w owns the FULL n=32
// gate-rows and strided 1/8 of K: chunks c = w + 8j (j=0..11; j<4 e, j>=4 h).
// h-part weight fragments REGISTER-RESIDENT (bh[8][8]); e-part weights in smem,
// ldmatrix'd inside the barrier shadow. NEW: out-projection fused — CTA c also
// computes out[:, t-1, 8*(c&15)..+8) via +1 HMMA per (j,m) reusing the same
// A-fragments (Wo slice in smem, ldm_x2 per j). Epilogue handles t = T-1.
#define SMEM_LSTM (32 * SW * 2 + 32 * SWE * 2 + 8 * GPL * 4 + 8 * SWO * 2 + 8 * OPL * 4)

__global__ void __launch_bounds__(256, 1) k_lstm(const float* __restrict__ bih,
                                                 const float* __restrict__ bhh,
                                                 float* __restrict__ out) {
    extern __shared__ char sm[];
    bf16*  As    = (bf16*)sm;                                           // 32 x SW
    bf16*  We    = (bf16*)(sm + 32 * SW * 2);                           // 32 x SWE
    float* gates = (float*)(sm + 32 * SW * 2 + 32 * SWE * 2);           // 8 planes
    bf16*  Wos   = (bf16*)(sm + 32 * SW * 2 + 32 * SWE * 2 + 8 * GPL * 4);  // 8 x SWO
    float* opl   = (float*)(sm + 32 * SW * 2 + 32 * SWE * 2 + 8 * GPL * 4 + 8 * SWO * 2);
    const int tid = threadIdx.x, lane = tid & 31, w = tid >> 5;
    const int cta = blockIdx.x;
    const int b_i = tid >> 3, jl = tid & 7;
    const int gcol = cta * 8 + jl;
    const int ocol = 8 * (cta & 15) + jl;      // my output column

    // ---- init: full weight slice 32x1536 -> As (temporarily) ----
    for (int i = tid; i < 6144; i += 256) {
        int r = i / 192, q = i - r * 192;
        *(uint4*)&As[r * SW + q * 8] = *(const uint4*)(g_Wc + ((size_t)cta * 32 + r) * KTOT + q * 8);
    }
    __syncthreads();

    // hoist h-part B fragments to registers (chunks w+32..w+88)
    const int bro0 = ((lane & 7) + ((lane >> 4) << 3));
    const int bco  = ((lane >> 3) & 1) * 8;
    uint32_t bh[8][8];
#pragma unroll
    for (int j = 0; j < 8; j++) {
        int col = (w + 8 * (j + 4)) * 16;
#pragma unroll
        for (int nt = 0; nt < 2; nt++)
            ldm_x4(&bh[j][nt * 4], smem_u32(&As[(nt * 16 + bro0) * SW + col + bco]));
    }
    // e-part weights gmem -> We (32 x 512)
    for (int i = tid; i < 2048; i += 256) {
        int r = i >> 6, q = i & 63;
        *(uint4*)&We[r * SWE + q * 8] = *(const uint4*)(g_Wc + ((size_t)cta * 32 + r) * KTOT + q * 8);
    }
    // Wo slice (8 rows x 1024) -> Wos
    for (int i = tid; i < 1024; i += 256) {
        int r = i >> 7, q = i & 127;
        *(uint4*)&Wos[r * SWO + q * 8] =
            *(const uint4*)(g_Wo + ((size_t)(8 * (cta & 15) + r)) * H_ + q * 8);
    }
    // bias (gates i,f,g,o at column gcol)
    const float bs0 = bih[gcol]          + bhh[gcol];
    const float bs1 = bih[H_ + gcol]     + bhh[H_ + gcol];
    const float bs2 = bih[2 * H_ + gcol] + bhh[2 * H_ + gcol];
    const float bs3 = bih[3 * H_ + gcol] + bhh[3 * H_ + gcol];
    __syncthreads();   // bh reads done + We/Wos written before As reuse

    const int arow0 = (lane & 15) * SW + ((lane >> 4) * 8);
    const int worow = (lane & 7) * SWO + bco;    // Wo frag address base

    float acc[2][4][4];
#pragma unroll
    for (int m = 0; m < 2; m++)
#pragma unroll
        for (int n = 0; n < 4; n++)
#pragma unroll
            for (int r = 0; r < 4; r++) acc[m][n][r] = 0.f;

    // ---- stage e_0, e-mma for t=0 ----
    uint4 ereg[8];
#pragma unroll
    for (int j = 0; j < 8; j++) {
        int idx = j * 256 + tid; int er = idx >> 6, eq = idx & 63;
        ereg[j] = *(const uint4*)(g_e + ((size_t)er * T_) * E_ + eq * 8);
    }
#pragma unroll
    for (int j = 0; j < 8; j++) {
        int idx = j * 256 + tid; int er = idx >> 6, eq = idx & 63;
        *(uint4*)&As[er * SW + eq * 8] = ereg[j];
    }
    __syncthreads();
#pragma unroll
    for (int j = 0; j < 4; j++) {
        int col = (w + 8 * j) * 16;
        uint32_t be[8];
        ldm_x4(be,     smem_u32(&We[(bro0) * SWE + col + bco]));
        ldm_x4(be + 4, smem_u32(&We[(16 + bro0) * SWE + col + bco]));
#pragma unroll
        for (int m = 0; m < 2; m++) {
            uint32_t af[4];
            ldm_x4(af, smem_u32(&As[m * 16 * SW + arow0 + col]));
            mma16816(acc[m][0], af, be);
            mma16816(acc[m][1], af, be + 2);
            mma16816(acc[m][2], af, be + 4);
            mma16816(acc[m][3], af, be + 6);
        }
    }

    float creg = 0.f;
    for (int t = 0; t < T_; t++) {
        const bf16* hsrc = g_hbuf[t & 1];
        // stage h [32][1024] into As cols 512..1536 (ldcg -> reg -> STS, proven)
        uint4 hreg[16];
#pragma unroll
        for (int j = 0; j < 16; j++) {
            int idx = j * 256 + tid; int hr = idx >> 7, hq = idx & 127;
            hreg[j] = __ldcg((const uint4*)(hsrc + (size_t)hr * H_ + hq * 8));
        }
#pragma unroll
        for (int j = 0; j < 16; j++) {
            int idx = j * 256 + tid; int hr = idx >> 7, hq = idx & 127;
            *(uint4*)&As[hr * SW + 512 + hq * 8] = hreg[j];
        }
        __syncthreads();

        // prefetch e_{t+1} (no dependency; hidden under h-mma)
        const int tn = (t + 1 < T_) ? t + 1 : T_ - 1;
#pragma unroll
        for (int j = 0; j < 8; j++) {
            int idx = j * 256 + tid; int er = idx >> 6, eq = idx & 63;
            ereg[j] = *(const uint4*)(g_e + ((size_t)er * T_ + tn) * E_ + eq * 8);
        }

        // h-mma: 8 chunks, register-resident B; + fused out-mma (reuses af)
        float oacc[2][4];
#pragma unroll
        for (int m = 0; m < 2; m++)
#pragma unroll
            for (int r = 0; r < 4; r++) oacc[m][r] = 0.f;
#pragma unroll
        for (int j = 0; j < 8; j++) {
            int col = (w + 8 * (j + 4)) * 16;
            uint32_t wf[2];
            ldm_x2(wf, smem_u32(&Wos[worow + 16 * w + 128 * j]));
#pragma unroll
            for (int m = 0; m < 2; m++) {
                uint32_t af[4];
                ldm_x4(af, smem_u32(&As[m * 16 * SW + arow0 + col]));
                mma16816(acc[m][0], af, bh[j]);
                mma16816(acc[m][1], af, bh[j] + 2);
                mma16816(acc[m][2], af, bh[j] + 4);
                mma16816(acc[m][3], af, bh[j] + 6);
                mma16816(oacc[m], af, wf);
            }
        }

        // write gate partials + out partials to plane w
        {
            float* gp = gates + w * GPL;
            float* op = opl + w * OPL;
            int mr = lane >> 2, mc = (lane & 3) * 2;
#pragma unroll
            for (int m = 0; m < 2; m++) {
#pragma unroll
                for (int n = 0; n < 4; n++) {
                    int row = m * 16 + mr, col = n * 8 + mc;
                    *(float2*)&gp[row * GST + col]       = make_float2(acc[m][n][0], acc[m][n][1]);
                    *(float2*)&gp[(row + 8) * GST + col] = make_float2(acc[m][n][2], acc[m][n][3]);
                }
                *(float2*)&op[(m * 16 + mr) * OST + mc]     = make_float2(oacc[m][0], oacc[m][1]);
                *(float2*)&op[(m * 16 + mr + 8) * OST + mc] = make_float2(oacc[m][2], oacc[m][3]);
            }
        }
        __syncthreads();

        // cell update for (batch b_i, column gcol): reduce 8 planes
        float pi = bs0, pf = bs1, pg = bs2, po = bs3;
#pragma unroll
        for (int p = 0; p < 8; p++) {
            const float* gq = gates + p * GPL + b_i * GST;
            pi += gq[jl];
            pf += gq[8 + jl];
            pg += gq[16 + jl];
            po += gq[24 + jl];
        }
        float ig = sigmoidf_(pi), fg = sigmoidf_(pf), og = sigmoidf_(po);
        float gg = tanhf(pg);
        creg = fg * creg + ig * gg;
        float h = og * tanhf(creg);
        bf16 hb = __float2bfloat16(h);
        g_hbuf[(t + 1) & 1][b_i * H_ + gcol] = hb;
        g_hs[((size_t)b_i * T_ + t) * H_ + gcol] = hb;

        // out row for time t-1 (h staged this step is hs[:, t-1])
        if (t > 0) {
            float ov = 0.f;
#pragma unroll
            for (int p = 0; p < 8; p++) ov += opl[p * OPL + b_i * OST + jl];
            out[((size_t)b_i * T_ + (t - 1)) * O_ + ocol] = ov;
        }

        // stage e_{t+1} into As cols 0..511 (readers finished at gates sync)
#pragma unroll
        for (int j = 0; j < 8; j++) {
            int idx = j * 256 + tid; int er = idx >> 6, eq = idx & 63;
            *(uint4*)&As[er * SW + eq * 8] = ereg[j];
        }
        __syncthreads();   // h stores + e staging done block-wide

        // release: one store publishes this CTA's h for step t+1
        if (tid == 0) {
            asm volatile("st.release.gpu.global.b32 [%0], %1;"
                         :: "l"(g_arrive + cta * 32), "r"(t + 1) : "memory");
        }

        // e-part mma for t+1 — runs in the barrier shadow
#pragma unroll
        for (int m = 0; m < 2; m++)
#pragma unroll
            for (int n = 0; n < 4; n++)
#pragma unroll
                for (int r = 0; r < 4; r++) acc[m][n][r] = 0.f;
#pragma unroll
        for (int j = 0; j < 4; j++) {
            int col = (w + 8 * j) * 16;
            uint32_t be[8];
            ldm_x4(be,     smem_u32(&We[(bro0) * SWE + col + bco]));
            ldm_x4(be + 4, smem_u32(&We[(16 + bro0) * SWE + col + bco]));
#pragma unroll
            for (int m = 0; m < 2; m++) {
                uint32_t af[4];
                ldm_x4(af, smem_u32(&As[m * 16 * SW + arow0 + col]));
                mma16816(acc[m][0], af, be);
                mma16816(acc[m][1], af, be + 2);
                mma16816(acc[m][2], af, be + 4);
                mma16816(acc[m][3], af, be + 6);
            }
        }

        // single-hop all-to-all barrier: thread i polls CTA i's flag
        if (tid < NCTA) {
            const int* fp = g_arrive + tid * 32;
            int v;
            do {
                asm volatile("ld.acquire.gpu.global.b32 %0, [%1];" : "=r"(v) : "l"(fp));
            } while (v < t + 1);
        }
        __syncthreads();
    }

    // ---- epilogue: out row for t = T-1 from final h (all CTAs synced above) ----
    {
        const bf16* hsrc = g_hbuf[T_ & 1];
        uint4 hreg[16];
#pragma unroll
        for (int j = 0; j < 16; j++) {
            int idx = j * 256 + tid; int hr = idx >> 7, hq = idx & 127;
            hreg[j] = __ldcg((const uint4*)(hsrc + (size_t)hr * H_ + hq * 8));
        }
#pragma unroll
        for (int j = 0; j < 16; j++) {
            int idx = j * 256 + tid; int hr = idx >> 7, hq = idx & 127;
            *(uint4*)&As[hr * SW + 512 + hq * 8] = hreg[j];
        }
        __syncthreads();

        float oacc[2][4];
#pragma unroll
        for (int m = 0; m < 2; m++)
#pragma unroll
            for (int r = 0; r < 4; r++) oacc[m][r] = 0.f;
#pragma unroll
        for (int j = 0; j < 8; j++) {
            int col = (w + 8 * (j + 4)) * 16;
            uint32_t wf[2];
            ldm_x2(wf, smem_u32(&Wos[worow + 16 * w + 128 * j]));
#pragma unroll
            for (int m = 0; m < 2; m++) {
                uint32_t af[4];
                ldm_x4(af, smem_u32(&As[m * 16 * SW + arow0 + col]));
                mma16816(oacc[m], af, wf);
            }
        }
        {
            float* op = opl + w * OPL;
            int mr = lane >> 2, mc = (lane & 3) * 2;
#pragma unroll
            for (int m = 0; m < 2; m++) {
                *(float2*)&op[(m * 16 + mr) * OST + mc]     = make_float2(oacc[m][0], oacc[m][1]);
                *(float2*)&op[(m * 16 + mr + 8) * OST + mc] = make_float2(oacc[m][2], oacc[m][3]);
            }
        }
        __syncthreads();
        float ov = 0.f;
#pragma unroll
        for (int p = 0; p < 8; p++) ov += opl[p * OPL + b_i * OST + jl];
        out[((size_t)b_i * T_ + (T_ - 1)) * O_ + ocol] = ov;
    }
}

// -------- verb logits (launch #4) --------
__global__ void k_vc(const int* __restrict__ vidx, const float* __restrict__ blin) {
    __shared__ bf16 vrow[H_];
    int b = blockIdx.x, tid = threadIdx.x;
    int t = vidx[b];
    for (int i = tid; i < H_; i += 128) vrow[i] = g_hs[((size_t)b * T_ + t) * H_ + i];
    __syncthreads();
    float s = 0.f;
    const uint4* wr4 = (const uint4*)(g_Wv + (size_t)tid * H_);
    const uint4* hv4 = (const uint4*)vrow;
#pragma unroll 4
    for (int k = 0; k < H_ / 8; k++) {
        uint4 wv = wr4[k];
        uint4 hv = hv4[k];
        const __nv_bfloat162* wp = (const __nv_bfloat162*)&wv;
        const __nv_bfloat162* hp = (const __nv_bfloat162*)&hv;
#pragma unroll
        for (int q = 0; q < 4; q++) {
            s += __bfloat162float(wp[q].x) * __bfloat162float(hp[q].x)
               + __bfloat162float(wp[q].y) * __bfloat162float(hp[q].y);
        }
    }
    g_vc[b * O_ + tid] = s + blin[tid];
}

// -------- fused add-verb-logits + log_softmax (launch #5) --------
__global__ void k_lsm(float* __restrict__ out) {
    int m = blockIdx.x, tid = threadIdx.x, w = tid >> 5;
    int b = m >> 9;
    float x = out[(size_t)m * O_ + tid] + g_vc[b * O_ + tid];
    float mx = x;
#pragma unroll
    for (int o = 16; o; o >>= 1) mx = fmaxf(mx, __shfl_xor_sync(0xffffffffu, mx, o));
    __shared__ float s1[4], s2[4];
    if ((tid & 31) == 0) s1[w] = mx;
    __syncthreads();
    mx = fmaxf(fmaxf(s1[0], s1[1]), fmaxf(s1[2], s1[3]));
    float e = __expf(x - mx);
    float sm = e;
#pragma unroll
    for (int o = 16; o; o >>= 1) sm += __shfl_xor_sync(0xffffffffu, sm, o);
    if ((tid & 31) == 0) s2[w] = sm;
    __syncthreads();
    sm = s2[0] + s2[1] + s2[2] + s2[3];
    out[(size_t)m * O_ + tid] = x - mx - __logf(sm);
}

extern "C" void kernel_launch(void* const* d_in, const int* in_sizes, int n_in,
                              void* d_out, int out_size) {
    const int*   tokens = (const int*)d_in[0];
    const int*   vidx   = (const int*)d_in[1];
    const float* emb    = (const float*)d_in[2];
    const float* W_ih   = (const float*)d_in[3];
    const float* W_hh   = (const float*)d_in[4];
    const float* b_ih   = (const float*)d_in[5];
    const float* b_hh   = (const float*)d_in[6];
    const float* W_lin  = (const float*)d_in[7];
    const float* b_lin  = (const float*)d_in[8];
    float* out = (float*)d_out;

    static int smem_set = 0;
    if (!smem_set) {
        cudaFuncSetAttribute(k_lstm, cudaFuncAttributeMaxDynamicSharedMemorySize, SMEM_LSTM);
        smem_set = 1;
    }

    // #0: init + gather
    k_prep1<<<(B_ * T_ * E_ / 4) / 256, 256>>>(tokens, emb);
    // #1: pack [W_ih|W_hh] per CTA
    k_prep2<<<(NCTA * 32 * KTOT / 8) / 256, 256>>>(W_ih, W_hh);
    // #2: split W_lin
    k_prep3<<<(O_ * 2 * H_ / 4) / 256, 256>>>(W_lin);
    // #3: fused persistent LSTM + out-projection (profiled slot)
    k_lstm<<<NCTA, 256, SMEM_LSTM>>>(b_ih, b_hh, out);
    // #4/#5: verb logits + fused log_softmax
    k_vc<<<B_, 128>>>(vidx, b_lin);
    k_lsm<<<B_ * T_, 128>>>(out);
}

// round 16
// speedup vs baseline: 1.4663x; 1.0651x over previous
#include <cuda_runtime.h>
#include <cuda_bf16.h>
#include <cstdint>

typedef __nv_bfloat16 bf16;

#define B_ 32
#define T_ 512
#define E_ 512
#define H_ 1024
#define O_ 128
#define NCTA 128
#define KTOT 1536          // 512 (e) + 1024 (h)
#define SW 1544            // As row stride (elems); conflict-free ldmatrix
#define SWE 520            // We row stride (elems)
#define SWO 1032           // Wo_s row stride (elems)
#define GST 40             // gates row stride (floats)
#define GPL (32 * GST)     // gate plane floats
#define OST 12             // out-plane row stride (floats)
#define OPL (32 * OST)     // out plane floats

// ---------------- scratch (static device globals; no allocs) ----------------
__device__ __align__(16) bf16  g_e[B_ * T_ * E_];              // embeddings bf16 [B][T][E]
__device__ __align__(16) bf16  g_Wc[(size_t)NCTA * 32 * KTOT]; // per-CTA packed [Wih|Whh]
__device__ __align__(16) bf16  g_Wo[O_ * H_];                  // W_lin[:,H:2H]
__device__ __align__(16) bf16  g_Wv[O_ * H_];                  // W_lin[:,0:H]
__device__ __align__(16) bf16  g_hs[(size_t)B_ * T_ * H_];     // hidden states [B][T][H]
__device__ __align__(16) bf16  g_hbuf[2][B_ * H_];             // h double buffer
__device__ float g_vc[B_ * O_];
__device__ __align__(128) int g_arrive[NCTA * 32];             // 1 flag per CTA, 128B apart

// ---------------- PTX helpers ----------------
__device__ __forceinline__ uint32_t smem_u32(const void* p) {
    return (uint32_t)__cvta_generic_to_shared(p);
}
__device__ __forceinline__ void ldm_x4(uint32_t* r, uint32_t a) {
    asm volatile("ldmatrix.sync.aligned.m8n8.x4.shared.b16 {%0,%1,%2,%3}, [%4];"
                 : "=r"(r[0]), "=r"(r[1]), "=r"(r[2]), "=r"(r[3]) : "r"(a));
}
__device__ __forceinline__ void ldm_x2(uint32_t* r, uint32_t a) {
    asm volatile("ldmatrix.sync.aligned.m8n8.x2.shared.b16 {%0,%1}, [%2];"
                 : "=r"(r[0]), "=r"(r[1]) : "r"(a));
}
__device__ __forceinline__ void mma16816(float* d, const uint32_t* a, const uint32_t* b) {
    asm volatile(
        "mma.sync.aligned.m16n8k16.row.col.f32.bf16.bf16.f32 "
        "{%0,%1,%2,%3}, {%4,%5,%6,%7}, {%8,%9}, {%0,%1,%2,%3};\n"
        : "+f"(d[0]), "+f"(d[1]), "+f"(d[2]), "+f"(d[3])
        : "r"(a[0]), "r"(a[1]), "r"(a[2]), "r"(a[3]), "r"(b[0]), "r"(b[1]));
}
__device__ __forceinline__ float sigmoidf_(float x) { return 1.f / (1.f + __expf(-x)); }

// ------------- prep1 (launch #0): init state + embedding gather -------------
__global__ void k_prep1(const int* __restrict__ tok, const float* __restrict__ emb) {
    int i = blockIdx.x * 256 + threadIdx.x;   // B*T*E/4 quads
    if (i < NCTA * 32) g_arrive[i] = 0;
    if (i < 2 * B_ * H_ / 8) ((uint4*)g_hbuf)[i] = make_uint4(0, 0, 0, 0);
    int m = i >> 7;                           // row in [0, B*T)
    int q = i & 127;
    int t = tok[m];
    float4 v = *(const float4*)(emb + (size_t)t * E_ + q * 4);
    __nv_bfloat162* d2 = (__nv_bfloat162*)(g_e + (size_t)m * E_ + q * 4);
    d2[0] = __floats2bfloat162_rn(v.x, v.y);
    d2[1] = __floats2bfloat162_rn(v.z, v.w);
}

// ------- prep2 (launch #1): pack [W_ih | W_hh] gate rows per CTA -> g_Wc -------
// packed row r of CTA c: gate g = r>>3, jl = r&7  ->  original row g*H + c*8 + jl
__global__ void k_prep2(const float* __restrict__ wih, const float* __restrict__ whh) {
    int idx = blockIdx.x * 256 + threadIdx.x;          // NCTA*32*KTOT/8 items
    int j = idx * 8;
    int k = j % KTOT;
    int r = (j / KTOT) & 31;
    int c = j / (KTOT * 32);
    int row = (r >> 3) * H_ + c * 8 + (r & 7);
    const float* src = (k < E_) ? (wih + (size_t)row * E_ + k)
                                : (whh + (size_t)row * H_ + (k - E_));
    float4 a = *(const float4*)src;
    float4 b = *(const float4*)(src + 4);
    __nv_bfloat162 o[4];
    o[0] = __floats2bfloat162_rn(a.x, a.y);
    o[1] = __floats2bfloat162_rn(a.z, a.w);
    o[2] = __floats2bfloat162_rn(b.x, b.y);
    o[3] = __floats2bfloat162_rn(b.z, b.w);
    *(uint4*)(g_Wc + (size_t)j) = *(uint4*)o;
}

// ------------- prep3 (launch #2): split W_lin into Wv / Wo -------------
__global__ void k_prep3(const float* __restrict__ wlin) {
    int idx = blockIdx.x * 256 + threadIdx.x;   // O*2H/4 items
    int j = idx * 4;
    int o = j >> 11;
    int k = j & 2047;
    float4 v = *(const float4*)(wlin + j);
    __nv_bfloat162 p0 = __floats2bfloat162_rn(v.x, v.y);
    __nv_bfloat162 p1 = __floats2bfloat162_rn(v.z, v.w);
    bf16* dst = (k < H_) ? (g_Wv + o * H_ + k) : (g_Wo + o * H_ + (k - H_));
    ((__nv_bfloat162*)dst)[0] = p0;
    ((__nv_bfloat162*)dst)[1] = p1;
}

// ---------------- fused persistent LSTM + output proj (launch #3) ----------------
// 128 CTAs x 256 threads = 8 warps. Warp w: full N=32 gate rows, strided 1/8 of
// K. h-weights (bh[8][8]) AND Wo fragments (wf[8][2]) register-resident.
// Fine-grained grid sync: thread tid serves producer CTA p = tid>>1 — polls
// flag[p] only, then loads/stages that producer's h columns (one uint4/row).
// The dedicated barrier phase is gone; sync1 joins the staging.
#define SMEM_LSTM (32 * SW * 2 + 32 * SWE * 2 + 8 * GPL * 4 + 8 * SWO * 2 + 8 * OPL * 4)

__global__ void __launch_bounds__(256, 1) k_lstm(const float* __restrict__ bih,
                                                 const float* __restrict__ bhh,
                                                 float* __restrict__ out) {
    extern __shared__ char sm[];
    bf16*  As    = (bf16*)sm;                                           // 32 x SW
    bf16*  We    = (bf16*)(sm + 32 * SW * 2);                           // 32 x SWE
    float* gates = (float*)(sm + 32 * SW * 2 + 32 * SWE * 2);           // 8 planes
    bf16*  Wos   = (bf16*)(sm + 32 * SW * 2 + 32 * SWE * 2 + 8 * GPL * 4);  // 8 x SWO
    float* opl   = (float*)(sm + 32 * SW * 2 + 32 * SWE * 2 + 8 * GPL * 4 + 8 * SWO * 2);
    const int tid = threadIdx.x, lane = tid & 31, w = tid >> 5;
    const int cta = blockIdx.x;
    const int b_i = tid >> 3, jl = tid & 7;
    const int gcol = cta * 8 + jl;
    const int ocol = 8 * (cta & 15) + jl;      // my output column
    const int prod = tid >> 1;                 // producer CTA I stage from
    const int hf   = tid & 1;                  // row half (0: rows 0-15, 1: 16-31)

    // ---- init: full weight slice 32x1536 -> As (temporarily) ----
    for (int i = tid; i < 6144; i += 256) {
        int r = i / 192, q = i - r * 192;
        *(uint4*)&As[r * SW + q * 8] = *(const uint4*)(g_Wc + ((size_t)cta * 32 + r) * KTOT + q * 8);
    }
    // Wo slice (8 rows x 1024) -> Wos
    for (int i = tid; i < 1024; i += 256) {
        int r = i >> 7, q = i & 127;
        *(uint4*)&Wos[r * SWO + q * 8] =
            *(const uint4*)(g_Wo + ((size_t)(8 * (cta & 15) + r)) * H_ + q * 8);
    }
    __syncthreads();

    // hoist h-part B fragments to registers (chunks w+32..w+88)
    const int bro0 = ((lane & 7) + ((lane >> 4) << 3));
    const int bco  = ((lane >> 3) & 1) * 8;
    uint32_t bh[8][8];
#pragma unroll
    for (int j = 0; j < 8; j++) {
        int col = (w + 8 * (j + 4)) * 16;
#pragma unroll
        for (int nt = 0; nt < 2; nt++)
            ldm_x4(&bh[j][nt * 4], smem_u32(&As[(nt * 16 + bro0) * SW + col + bco]));
    }
    // hoist Wo fragments to registers (time-invariant)
    const int worow = (lane & 7) * SWO + bco;
    uint32_t wf[8][2];
#pragma unroll
    for (int j = 0; j < 8; j++)
        ldm_x2(wf[j], smem_u32(&Wos[worow + 16 * w + 128 * j]));

    // e-part weights gmem -> We (32 x 512)
    for (int i = tid; i < 2048; i += 256) {
        int r = i >> 6, q = i & 63;
        *(uint4*)&We[r * SWE + q * 8] = *(const uint4*)(g_Wc + ((size_t)cta * 32 + r) * KTOT + q * 8);
    }
    // bias (gates i,f,g,o at column gcol)
    const float bs0 = bih[gcol]          + bhh[gcol];
    const float bs1 = bih[H_ + gcol]     + bhh[H_ + gcol];
    const float bs2 = bih[2 * H_ + gcol] + bhh[2 * H_ + gcol];
    const float bs3 = bih[3 * H_ + gcol] + bhh[3 * H_ + gcol];
    __syncthreads();   // bh/wf reads done + We written before As reuse

    const int arow0 = (lane & 15) * SW + ((lane >> 4) * 8);

    float acc[2][4][4];
#pragma unroll
    for (int m = 0; m < 2; m++)
#pragma unroll
        for (int n = 0; n < 4; n++)
#pragma unroll
            for (int r = 0; r < 4; r++) acc[m][n][r] = 0.f;

    // ---- stage e_0, e-mma for t=0 ----
    uint4 ereg[8];
#pragma unroll
    for (int j = 0; j < 8; j++) {
        int idx = j * 256 + tid; int er = idx >> 6, eq = idx & 63;
        ereg[j] = *(const uint4*)(g_e + ((size_t)er * T_) * E_ + eq * 8);
    }
#pragma unroll
    for (int j = 0; j < 8; j++) {
        int idx = j * 256 + tid; int er = idx >> 6, eq = idx & 63;
        *(uint4*)&As[er * SW + eq * 8] = ereg[j];
    }
    __syncthreads();
#pragma unroll
    for (int j = 0; j < 4; j++) {
        int col = (w + 8 * j) * 16;
        uint32_t be[8];
        ldm_x4(be,     smem_u32(&We[(bro0) * SWE + col + bco]));
        ldm_x4(be + 4, smem_u32(&We[(16 + bro0) * SWE + col + bco]));
#pragma unroll
        for (int m = 0; m < 2; m++) {
            uint32_t af[4];
            ldm_x4(af, smem_u32(&As[m * 16 * SW + arow0 + col]));
            mma16816(acc[m][0], af, be);
            mma16816(acc[m][1], af, be + 2);
            mma16816(acc[m][2], af, be + 4);
            mma16816(acc[m][3], af, be + 6);
        }
    }

    float creg = 0.f;
    for (int t = 0; t < T_; t++) {
        const bf16* hsrc = g_hbuf[t & 1];
        // fine-grained sync: wait for MY producer only, then load its columns
        {
            const int* fp = g_arrive + prod * 32;
            int v;
            do {
                asm volatile("ld.acquire.gpu.global.b32 %0, [%1];" : "=r"(v) : "l"(fp));
            } while (v < t);
        }
        uint4 hreg[16];
#pragma unroll
        for (int r = 0; r < 16; r++)
            hreg[r] = __ldcg((const uint4*)(hsrc + (size_t)(hf * 16 + r) * H_ + prod * 8));

        // prefetch e_{t+1} (no dependency; hidden under h-mma)
        const int tn = (t + 1 < T_) ? t + 1 : T_ - 1;
#pragma unroll
        for (int j = 0; j < 8; j++) {
            int idx = j * 256 + tid; int er = idx >> 6, eq = idx & 63;
            ereg[j] = *(const uint4*)(g_e + ((size_t)er * T_ + tn) * E_ + eq * 8);
        }
#pragma unroll
        for (int r = 0; r < 16; r++)
            *(uint4*)&As[(hf * 16 + r) * SW + 512 + prod * 8] = hreg[r];
        __syncthreads();   // sync1: all producers' h staged (joins the fine sync)

        // h-mma: 8 chunks, register-resident B; fused out-mma (register wf)
        float oacc[2][4];
#pragma unroll
        for (int m = 0; m < 2; m++)
#pragma unroll
            for (int r = 0; r < 4; r++) oacc[m][r] = 0.f;
#pragma unroll
        for (int j = 0; j < 8; j++) {
            int col = (w + 8 * (j + 4)) * 16;
#pragma unroll
            for (int m = 0; m < 2; m++) {
                uint32_t af[4];
                ldm_x4(af, smem_u32(&As[m * 16 * SW + arow0 + col]));
                mma16816(acc[m][0], af, bh[j]);
                mma16816(acc[m][1], af, bh[j] + 2);
                mma16816(acc[m][2], af, bh[j] + 4);
                mma16816(acc[m][3], af, bh[j] + 6);
                mma16816(oacc[m], af, wf[j]);
            }
        }

        // write gate partials + out partials to plane w
        {
            float* gp = gates + w * GPL;
            float* op = opl + w * OPL;
            int mr = lane >> 2, mc = (lane & 3) * 2;
#pragma unroll
            for (int m = 0; m < 2; m++) {
#pragma unroll
                for (int n = 0; n < 4; n++) {
                    int row = m * 16 + mr, col = n * 8 + mc;
                    *(float2*)&gp[row * GST + col]       = make_float2(acc[m][n][0], acc[m][n][1]);
                    *(float2*)&gp[(row + 8) * GST + col] = make_float2(acc[m][n][2], acc[m][n][3]);
                }
                *(float2*)&op[(m * 16 + mr) * OST + mc]     = make_float2(oacc[m][0], oacc[m][1]);
                *(float2*)&op[(m * 16 + mr + 8) * OST + mc] = make_float2(oacc[m][2], oacc[m][3]);
            }
        }
        __syncthreads();   // sync2: gates/out planes visible

        // cell update for (batch b_i, column gcol): reduce 8 planes
        float pi = bs0, pf = bs1, pg = bs2, po = bs3;
#pragma unroll
        for (int p = 0; p < 8; p++) {
            const float* gq = gates + p * GPL + b_i * GST;
            pi += gq[jl];
            pf += gq[8 + jl];
            pg += gq[16 + jl];
            po += gq[24 + jl];
        }
        float ig = sigmoidf_(pi), fg = sigmoidf_(pf), og = sigmoidf_(po);
        float gg = tanhf(pg);
        creg = fg * creg + ig * gg;
        float h = og * tanhf(creg);
        bf16 hb = __float2bfloat16(h);
        g_hbuf[(t + 1) & 1][b_i * H_ + gcol] = hb;

        // out row for time t-1 (h staged this step is hs[:, t-1])
        if (t > 0) {
            float ov = 0.f;
#pragma unroll
            for (int p = 0; p < 8; p++) ov += opl[p * OPL + b_i * OST + jl];
            out[((size_t)b_i * T_ + (t - 1)) * O_ + ocol] = ov;
        }

        // stage e_{t+1} into As cols 0..511 (readers finished at sync2)
#pragma unroll
        for (int j = 0; j < 8; j++) {
            int idx = j * 256 + tid; int er = idx >> 6, eq = idx & 63;
            *(uint4*)&As[er * SW + eq * 8] = ereg[j];
        }
        __syncthreads();   // sync3: hbuf stores + e staging done block-wide

        // release: one store publishes this CTA's h for step t+1
        if (tid == 0) {
            asm volatile("st.release.gpu.global.b32 [%0], %1;"
                         :: "l"(g_arrive + cta * 32), "r"(t + 1) : "memory");
        }
        // archive AFTER release (not drained by it; visible at kernel end)
        __stcs(&g_hs[((size_t)b_i * T_ + t) * H_ + gcol], hb);

        // e-part mma for t+1 — runs in the flag-propagation shadow
#pragma unroll
        for (int m = 0; m < 2; m++)
#pragma unroll
            for (int n = 0; n < 4; n++)
#pragma unroll
                for (int r = 0; r < 4; r++) acc[m][n][r] = 0.f;
#pragma unroll
        for (int j = 0; j < 4; j++) {
            int col = (w + 8 * j) * 16;
            uint32_t be[8];
            ldm_x4(be,     smem_u32(&We[(bro0) * SWE + col + bco]));
            ldm_x4(be + 4, smem_u32(&We[(16 + bro0) * SWE + col + bco]));
#pragma unroll
            for (int m = 0; m < 2; m++) {
                uint32_t af[4];
                ldm_x4(af, smem_u32(&As[m * 16 * SW + arow0 + col]));
                mma16816(acc[m][0], af, be);
                mma16816(acc[m][1], af, be + 2);
                mma16816(acc[m][2], af, be + 4);
                mma16816(acc[m][3], af, be + 6);
            }
        }
        // loop back: fine-grained poll is the barrier
    }

    // ---- epilogue: out row for t = T-1 from final h ----
    {
        // confirm all producers reached T (each thread its own producer; sync joins)
        {
            const int* fp = g_arrive + prod * 32;
            int v;
            do {
                asm volatile("ld.acquire.gpu.global.b32 %0, [%1];" : "=r"(v) : "l"(fp));
            } while (v < T_);
        }
        __syncthreads();
        const bf16* hsrc = g_hbuf[T_ & 1];
        uint4 hreg[16];
#pragma unroll
        for (int r = 0; r < 16; r++)
            hreg[r] = __ldcg((const uint4*)(hsrc + (size_t)(hf * 16 + r) * H_ + prod * 8));
#pragma unroll
        for (int r = 0; r < 16; r++)
            *(uint4*)&As[(hf * 16 + r) * SW + 512 + prod * 8] = hreg[r];
        __syncthreads();

        float oacc[2][4];
#pragma unroll
        for (int m = 0; m < 2; m++)
#pragma unroll
            for (int r = 0; r < 4; r++) oacc[m][r] = 0.f;
#pragma unroll
        for (int j = 0; j < 8; j++) {
            int col = (w + 8 * (j + 4)) * 16;
#pragma unroll
            for (int m = 0; m < 2; m++) {
                uint32_t af[4];
                ldm_x4(af, smem_u32(&As[m * 16 * SW + arow0 + col]));
                mma16816(oacc[m], af, wf[j]);
            }
        }
        {
            float* op = opl + w * OPL;
            int mr = lane >> 2, mc = (lane & 3) * 2;
#pragma unroll
            for (int m = 0; m < 2; m++) {
                *(float2*)&op[(m * 16 + mr) * OST + mc]     = make_float2(oacc[m][0], oacc[m][1]);
                *(float2*)&op[(m * 16 + mr + 8) * OST + mc] = make_float2(oacc[m][2], oacc[m][3]);
            }
        }
        __syncthreads();
        float ov = 0.f;
#pragma unroll
        for (int p = 0; p < 8; p++) ov += opl[p * OPL + b_i * OST + jl];
        out[((size_t)b_i * T_ + (T_ - 1)) * O_ + ocol] = ov;
    }
}

// -------- verb logits (launch #4) --------
__global__ void k_vc(const int* __restrict__ vidx, const float* __restrict__ blin) {
    __shared__ bf16 vrow[H_];
    int b = blockIdx.x, tid = threadIdx.x;
    int t = vidx[b];
    for (int i = tid; i < H_; i += 128) vrow[i] = g_hs[((size_t)b * T_ + t) * H_ + i];
    __syncthreads();
    float s = 0.f;
    const uint4* wr4 = (const uint4*)(g_Wv + (size_t)tid * H_);
    const uint4* hv4 = (const uint4*)vrow;
#pragma unroll 4
    for (int k = 0; k < H_ / 8; k++) {
        uint4 wv = wr4[k];
        uint4 hv = hv4[k];
        const __nv_bfloat162* wp = (const __nv_bfloat162*)&wv;
        const __nv_bfloat162* hp = (const __nv_bfloat162*)&hv;
#pragma unroll
        for (int q = 0; q < 4; q++) {
            s += __bfloat162float(wp[q].x) * __bfloat162float(hp[q].x)
               + __bfloat162float(wp[q].y) * __bfloat162float(hp[q].y);
        }
    }
    g_vc[b * O_ + tid] = s + blin[tid];
}

// -------- fused add-verb-logits + log_softmax (launch #5) --------
__global__ void k_lsm(float* __restrict__ out) {
    int m = blockIdx.x, tid = threadIdx.x, w = tid >> 5;
    int b = m >> 9;
    float x = out[(size_t)m * O_ + tid] + g_vc[b * O_ + tid];
    float mx = x;
#pragma unroll
    for (int o = 16; o; o >>= 1) mx = fmaxf(mx, __shfl_xor_sync(0xffffffffu, mx, o));
    __shared__ float s1[4], s2[4];
    if ((tid & 31) == 0) s1[w] = mx;
    __syncthreads();
    mx = fmaxf(fmaxf(s1[0], s1[1]), fmaxf(s1[2], s1[3]));
    float e = __expf(x - mx);
    float sm = e;
#pragma unroll
    for (int o = 16; o; o >>= 1) sm += __shfl_xor_sync(0xffffffffu, sm, o);
    if ((tid & 31) == 0) s2[w] = sm;
    __syncthreads();
    sm = s2[0] + s2[1] + s2[2] + s2[3];
    out[(size_t)m * O_ + tid] = x - mx - __logf(sm);
}

extern "C" void kernel_launch(void* const* d_in, const int* in_sizes, int n_in,
                              void* d_out, int out_size) {
    const int*   tokens = (const int*)d_in[0];
    const int*   vidx   = (const int*)d_in[1];
    const float* emb    = (const float*)d_in[2];
    const float* W_ih   = (const float*)d_in[3];
    const float* W_hh   = (const float*)d_in[4];
    const float* b_ih   = (const float*)d_in[5];
    const float* b_hh   = (const float*)d_in[6];
    const float* W_lin  = (const float*)d_in[7];
    const float* b_lin  = (const float*)d_in[8];
    float* out = (float*)d_out;

    static int smem_set = 0;
    if (!smem_set) {
        cudaFuncSetAttribute(k_lstm, cudaFuncAttributeMaxDynamicSharedMemorySize, SMEM_LSTM);
        smem_set = 1;
    }

    // #0: init + gather
    k_prep1<<<(B_ * T_ * E_ / 4) / 256, 256>>>(tokens, emb);
    // #1: pack [W_ih|W_hh] per CTA
    k_prep2<<<(NCTA * 32 * KTOT / 8) / 256, 256>>>(W_ih, W_hh);
    // #2: split W_lin
    k_prep3<<<(O_ * 2 * H_ / 4) / 256, 256>>>(W_lin);
    // #3: fused persistent LSTM + out-projection (profiled slot)
    k_lstm<<<NCTA, 256, SMEM_LSTM>>>(b_ih, b_hh, out);
    // #4/#5: verb logits + fused log_softmax
    k_vc<<<B_, 128>>>(vidx, b_lin);
    k_lsm<<<B_ * T_, 128>>>(out);
}